// round 8
// baseline (speedup 1.0000x reference)
#include <cuda_runtime.h>
#include <cuda_fp16.h>
#include <stdint.h>
#include <math.h>

#define Bsz 4
#define Tsz 2048
#define Dsz 1024
#define BT  (Bsz * Tsz)

typedef __half h16;

// ---------------- scratch (__device__ globals; allocation-free rule) -------
__device__ __align__(16) h16 g_s[(size_t)Bsz * Tsz * Tsz];   // fp16 scores
__device__ __align__(16) h16 g_xf[(size_t)BT * Dsz];
__device__ __align__(16) h16 g_wf[3][(size_t)Dsz * Dsz];     // [3072,1024]
__device__ __align__(16) h16 g_qkv[(size_t)BT * 3 * Dsz];    // [8192, 3072]
__device__ __align__(16) h16 g_pf[(size_t)Bsz * Tsz * Tsz];

// ---------------- low-level helpers (plain sm_80-era PTX only) --------------
__device__ __forceinline__ uint32_t smem_u32(const void* p) {
    uint32_t a;
    asm("{ .reg .u64 t; cvta.to.shared.u64 t, %1; cvt.u32.u64 %0, t; }"
        : "=r"(a) : "l"(p));
    return a;
}

#define CP_ASYNC16(dst, src) \
    asm volatile("cp.async.cg.shared.global [%0], [%1], 16;" \
                 :: "r"(dst), "l"(src))
#define CP_COMMIT() asm volatile("cp.async.commit_group;")
#define CP_WAIT1()  asm volatile("cp.async.wait_group 1;")

__device__ __forceinline__ void ldsm4(uint32_t& r0, uint32_t& r1,
                                      uint32_t& r2, uint32_t& r3,
                                      uint32_t addr) {
    asm volatile("ldmatrix.sync.aligned.m8n8.x4.shared.b16 {%0,%1,%2,%3}, [%4];"
                 : "=r"(r0), "=r"(r1), "=r"(r2), "=r"(r3) : "r"(addr));
}

__device__ __forceinline__ void ldsm4t(uint32_t& r0, uint32_t& r1,
                                       uint32_t& r2, uint32_t& r3,
                                       uint32_t addr) {
    asm volatile(
        "ldmatrix.sync.aligned.m8n8.x4.trans.shared.b16 {%0,%1,%2,%3}, [%4];"
        : "=r"(r0), "=r"(r1), "=r"(r2), "=r"(r3) : "r"(addr));
}

__device__ __forceinline__ void mma16816(float* d, const uint32_t* a,
                                         const uint32_t* b) {
    asm volatile(
        "mma.sync.aligned.m16n8k16.row.col.f32.f16.f16.f32 "
        "{%0,%1,%2,%3}, {%4,%5,%6,%7}, {%8,%9}, {%0,%1,%2,%3};"
        : "+f"(d[0]), "+f"(d[1]), "+f"(d[2]), "+f"(d[3])
        : "r"(a[0]), "r"(a[1]), "r"(a[2]), "r"(a[3]), "r"(b[0]), "r"(b[1]));
}

// ---------------- HMMA GEMM, CTA tile 128x256, warp tile 64x64 --------------
// C[M,N] = A[M,K] * op(B).  bnn=0: B is [N,K] (NT).  bnn=1: B is [K,N] (NN).
// fp16 operands, fp32 accumulate. lda/ldb/ldc row strides (elements).
// mode 0: full grid.
// mode 1: blockIdx.x is a linear lower-triangular tile index (S-GEMM).
// mode 2: kend = row0+128, heavy rows first (PV GEMM).
// ofp16: write C as fp16 (else fp32).
#define KC     64
#define BNT    256               // CTA N tile
#define ROWB   144               // 128B data + 16B pad per row
#define ROWBB  528               // NN B tile: 512B data + 16B pad per k-row
#define ATILE  (128 * ROWB)      // 18432 B
#define BTILE  (BNT * ROWB)      // 36864 B  (NN B: 64*528=33792 <= BTILE)
#define STGB   (ATILE + BTILE)   // 55296 B
#define NSTG   3
#define SMEMB  (NSTG * STGB)     // 165888 B

__global__ void __launch_bounds__(256) hgemm(
    const h16* __restrict__ Af, const h16* __restrict__ Bf,
    void* __restrict__ Cv, int K, int lda, int ldb, int ldc,
    int mode, int ofp16, int bnn, long long sA, long long sB, long long sC)
{
    const int bz = blockIdx.z;
    Af += (size_t)bz * sA;
    Bf += (size_t)bz * sB;

    int row0, col0;
    if (mode == 1) {
        // lower-triangular tiles over 128-rows x 256-cols:
        // row r (0..15) has r/2 + 1 col tiles
        int t = blockIdx.x, r = 0;
        while (t >= (r / 2 + 1)) { t -= r / 2 + 1; r++; }
        row0 = r * 128;
        col0 = t * BNT;
    } else if (mode == 2) {
        const int by = (int)gridDim.y - 1 - (int)blockIdx.y;  // heavy first
        row0 = by * 128;
        col0 = blockIdx.x * BNT;
    } else {
        row0 = blockIdx.y * 128;
        col0 = blockIdx.x * BNT;
    }
    const int kend = (mode == 2) ? (row0 + 128) : K;
    const int nc = kend / KC;           // >= 2 always

    extern __shared__ char smc[];
    const uint32_t smb = smem_u32(smc);
    const int tid  = threadIdx.x;
    const int lane = tid & 31;
    const int wid  = tid >> 5;
    const int m0 = (wid & 1) * 64;      // warp tile 64x64, warps 2x4
    const int n0 = (wid >> 1) * 64;

    float acc[4][8][4];
#pragma unroll
    for (int i = 0; i < 4; i++)
#pragma unroll
        for (int j = 0; j < 8; j++)
#pragma unroll
            for (int q = 0; q < 4; q++) acc[i][j][q] = 0.f;

    const int lch  = tid & 7;      // 16B chunk within 128B row
    const int lr0  = tid >> 3;     // 0..31
    const int lchn = tid & 31;     // NN B: 16B chunk within 512B row
    const int lrn  = tid >> 5;     // 0..7

    auto do_load = [&](int st, int k0) {
        const uint32_t sb = smb + (uint32_t)st * STGB;
        const h16* pA = Af + (size_t)row0 * lda + k0;
#pragma unroll
        for (int j = 0; j < 4; j++) {
            const int row = lr0 + j * 32;
            CP_ASYNC16(sb + (uint32_t)(row * ROWB + lch * 16),
                       pA + (size_t)row * lda + lch * 8);
        }
        if (!bnn) {
            const h16* pB = Bf + (size_t)col0 * ldb + k0;
#pragma unroll
            for (int j = 0; j < 8; j++) {          // 256 rows
                const int row = lr0 + j * 32;
                CP_ASYNC16(sb + ATILE + (uint32_t)(row * ROWB + lch * 16),
                           pB + (size_t)row * ldb + lch * 8);
            }
        } else {
            const h16* pB = Bf + (size_t)k0 * ldb + col0;
#pragma unroll
            for (int j = 0; j < 8; j++) {          // 64 k-rows x 32 chunks
                const int row = lrn + j * 8;
                CP_ASYNC16(sb + ATILE + (uint32_t)(row * ROWBB + lchn * 16),
                           pB + (size_t)row * ldb + lchn * 8);
            }
        }
    };

    do_load(0, 0);
    CP_COMMIT();
    do_load(1, KC);
    CP_COMMIT();

    for (int c = 0; c < nc; c++) {
        CP_WAIT1();                      // stage c resident
        __syncthreads();                 // all warps done with stage (c+2)%3
        if (c + 2 < nc) do_load((c + 2) % NSTG, (c + 2) * KC);
        CP_COMMIT();

        const uint32_t base = smb + (uint32_t)(c % NSTG) * STGB;
#pragma unroll
        for (int kk = 0; kk < 4; kk++) {          // four k16 steps per KC=64
            uint32_t a[4][4];
#pragma unroll
            for (int mi = 0; mi < 4; mi++) {
                const uint32_t ad = base +
                    (uint32_t)((m0 + mi * 16 + (lane & 15)) * ROWB +
                               (kk * 2 + (lane >> 4)) * 16);
                ldsm4(a[mi][0], a[mi][1], a[mi][2], a[mi][3], ad);
            }
            uint32_t bb[8][2];
            if (!bnn) {
#pragma unroll
                for (int np = 0; np < 4; np++) {  // [N,K]: non-trans ldsm
                    const int rb = n0 + np * 16 + (lane & 7) + ((lane >> 4) << 3);
                    const int ch = kk * 2 + ((lane >> 3) & 1);
                    const uint32_t ad = base + ATILE +
                        (uint32_t)(rb * ROWB + ch * 16);
                    ldsm4(bb[np*2][0], bb[np*2][1],
                          bb[np*2+1][0], bb[np*2+1][1], ad);
                }
            } else {
#pragma unroll
                for (int g = 0; g < 4; g++) {     // [K,N]: trans ldsm
                    const uint32_t ad = base + ATILE +
                        (uint32_t)((kk * 16 + (lane & 15)) * ROWBB +
                                   (n0 + g * 16 + ((lane >> 4) << 3)) * 2);
                    ldsm4t(bb[g*2][0], bb[g*2][1],
                           bb[g*2+1][0], bb[g*2+1][1], ad);
                }
            }
#pragma unroll
            for (int mi = 0; mi < 4; mi++)
#pragma unroll
                for (int ni = 0; ni < 8; ni++)
                    mma16816(acc[mi][ni], a[mi], bb[ni]);
        }
    }

    // epilogue
    const int er = lane >> 2;
    const int ec = (lane & 3) * 2;
    if (!ofp16) {
        float* C = (float*)Cv + (size_t)bz * sC;
#pragma unroll
        for (int mi = 0; mi < 4; mi++) {
            const int r = row0 + m0 + mi * 16 + er;
#pragma unroll
            for (int ni = 0; ni < 8; ni++) {
                const int cc = col0 + n0 + ni * 8 + ec;
                *(float2*)&C[(size_t)r * ldc + cc] =
                    make_float2(acc[mi][ni][0], acc[mi][ni][1]);
                *(float2*)&C[(size_t)(r + 8) * ldc + cc] =
                    make_float2(acc[mi][ni][2], acc[mi][ni][3]);
            }
        }
    } else {
        h16* C = (h16*)Cv + (size_t)bz * sC;
#pragma unroll
        for (int mi = 0; mi < 4; mi++) {
            const int r = row0 + m0 + mi * 16 + er;
#pragma unroll
            for (int ni = 0; ni < 8; ni++) {
                const int cc = col0 + n0 + ni * 8 + ec;
                __half2 h0 = __floats2half2_rn(acc[mi][ni][0], acc[mi][ni][1]);
                __half2 h1 = __floats2half2_rn(acc[mi][ni][2], acc[mi][ni][3]);
                *(__half2*)&C[(size_t)r * ldc + cc] = h0;
                *(__half2*)&C[(size_t)(r + 8) * ldc + cc] = h1;
            }
        }
    }
}

// ---------------- conversions ------------------------------------------------
__global__ void __launch_bounds__(256) conv_single(
    const float* __restrict__ in, h16* __restrict__ o, int n4)
{
    int i = blockIdx.x * 256 + threadIdx.x;
    if (i >= n4) return;
    float4 v = ((const float4*)in)[i];
    __half2 p0 = __floats2half2_rn(v.x, v.y);
    __half2 p1 = __floats2half2_rn(v.z, v.w);
    uint2 u;
    u.x = *(uint32_t*)&p0;
    u.y = *(uint32_t*)&p1;
    ((uint2*)o)[i] = u;
}

__global__ void __launch_bounds__(256) conv_w3(
    const float* __restrict__ w0, const float* __restrict__ w1,
    const float* __restrict__ w2, h16* __restrict__ o, int n4each)
{
    int i = blockIdx.x * 256 + threadIdx.x;
    if (i >= 3 * n4each) return;
    const int m = i / n4each;
    const int r = i - m * n4each;
    const float* in = (m == 0) ? w0 : (m == 1) ? w1 : w2;
    float4 v = ((const float4*)in)[r];
    __half2 p0 = __floats2half2_rn(v.x, v.y);
    __half2 p1 = __floats2half2_rn(v.z, v.w);
    uint2 u;
    u.x = *(uint32_t*)&p0;
    u.y = *(uint32_t*)&p1;
    ((uint2*)o)[i] = u;
}

// ---------------- causal softmax over fp16 S -> fp16 P ----------------------
__device__ __forceinline__ float warp_max_f(float v) {
#pragma unroll
    for (int o = 16; o; o >>= 1) v = fmaxf(v, __shfl_xor_sync(0xffffffffu, v, o));
    return v;
}
__device__ __forceinline__ float warp_sum_f(float v) {
#pragma unroll
    for (int o = 16; o; o >>= 1) v += __shfl_xor_sync(0xffffffffu, v, o);
    return v;
}

__global__ void __launch_bounds__(256) softmax_pf(
    const h16* __restrict__ S, h16* __restrict__ pf)
{
    __shared__ float es[Tsz];
    __shared__ float red[8];
    const int b = blockIdx.y;
    const int r = blockIdx.x;
    const h16* row = S + ((size_t)b * Tsz + r) * Tsz;
    h16* pr = pf + ((size_t)b * Tsz + r) * Tsz;
    const int blk_end = ((r >> 7) + 1) << 7;   // padded to 128
    const int n8 = blk_end >> 3;
    const float scale = 0.03125f;              // 1/sqrt(1024)
    const int tid = threadIdx.x;

    // pass 1: masked max (8 halves per load)
    float m = -INFINITY;
    for (int i8 = tid; i8 < n8; i8 += 256) {
        uint4 u = ((const uint4*)row)[i8];
        float2 f0 = __half22float2(*(__half2*)&u.x);
        float2 f1 = __half22float2(*(__half2*)&u.y);
        float2 f2 = __half22float2(*(__half2*)&u.z);
        float2 f3 = __half22float2(*(__half2*)&u.w);
        const int base = i8 << 3;
        if (base + 7 <= r) {
            m = fmaxf(m, fmaxf(fmaxf(f0.x, f0.y), fmaxf(f1.x, f1.y)));
            m = fmaxf(m, fmaxf(fmaxf(f2.x, f2.y), fmaxf(f3.x, f3.y)));
        } else {
            float vv[8] = {f0.x, f0.y, f1.x, f1.y, f2.x, f2.y, f3.x, f3.y};
#pragma unroll
            for (int j = 0; j < 8; j++)
                if (base + j <= r) m = fmaxf(m, vv[j]);
        }
    }
    m = warp_max_f(m);
    if ((tid & 31) == 0) red[tid >> 5] = m;
    __syncthreads();
    m = red[0];
#pragma unroll
    for (int i = 1; i < 8; i++) m = fmaxf(m, red[i]);
    __syncthreads();

    // pass 2: masked exp + sum (masked lanes contribute exact 0)
    float ssum = 0.f;
    for (int i8 = tid; i8 < n8; i8 += 256) {
        uint4 u = ((const uint4*)row)[i8];
        float2 f0 = __half22float2(*(__half2*)&u.x);
        float2 f1 = __half22float2(*(__half2*)&u.y);
        float2 f2 = __half22float2(*(__half2*)&u.z);
        float2 f3 = __half22float2(*(__half2*)&u.w);
        float vv[8] = {f0.x, f0.y, f1.x, f1.y, f2.x, f2.y, f3.x, f3.y};
        const int base = i8 << 3;
        float e[8];
#pragma unroll
        for (int j = 0; j < 8; j++) {
            e[j] = (base + j <= r) ? __expf((vv[j] - m) * scale) : 0.f;
            ssum += e[j];
        }
        ((float4*)es)[i8 * 2 + 0] = make_float4(e[0], e[1], e[2], e[3]);
        ((float4*)es)[i8 * 2 + 1] = make_float4(e[4], e[5], e[6], e[7]);
    }
    ssum = warp_sum_f(ssum);
    if ((tid & 31) == 0) red[tid >> 5] = ssum;
    __syncthreads();
    ssum = 0.f;
#pragma unroll
    for (int i = 0; i < 8; i++) ssum += red[i];
    const float inv = 1.f / ssum;
    __syncthreads();

    // pass 3: normalize + write fp16 (tail zeros come for free)
    for (int i8 = tid; i8 < n8; i8 += 256) {
        float4 e0 = ((const float4*)es)[i8 * 2 + 0];
        float4 e1 = ((const float4*)es)[i8 * 2 + 1];
        __half2 h0 = __floats2half2_rn(e0.x * inv, e0.y * inv);
        __half2 h1 = __floats2half2_rn(e0.z * inv, e0.w * inv);
        __half2 h2 = __floats2half2_rn(e1.x * inv, e1.y * inv);
        __half2 h3 = __floats2half2_rn(e1.z * inv, e1.w * inv);
        uint4 u;
        u.x = *(uint32_t*)&h0;
        u.y = *(uint32_t*)&h1;
        u.z = *(uint32_t*)&h2;
        u.w = *(uint32_t*)&h3;
        ((uint4*)pr)[i8] = u;
    }
}

// ---------------- launch ------------------------------------------------------
extern "C" void kernel_launch(void* const* d_in, const int* in_sizes, int n_in,
                              void* d_out, int out_size)
{
    (void)in_sizes; (void)n_in; (void)out_size;
    const float* x = (const float*)d_in[0];
    float* out = (float*)d_out;

    h16 *s, *xf, *wf, *qkv, *pf;
    cudaGetSymbolAddress((void**)&s,   g_s);
    cudaGetSymbolAddress((void**)&xf,  g_xf);
    cudaGetSymbolAddress((void**)&wf,  g_wf);
    cudaGetSymbolAddress((void**)&qkv, g_qkv);
    cudaGetSymbolAddress((void**)&pf,  g_pf);

    cudaFuncSetAttribute(hgemm, cudaFuncAttributeMaxDynamicSharedMemorySize,
                         SMEMB);

    const int nX = BT * Dsz;    // 8M
    const int nW = Dsz * Dsz;   // 1M

    conv_single<<<nX / 4 / 256, 256>>>(x, xf, nX / 4);
    conv_w3<<<3 * (nW / 4) / 256, 256>>>((const float*)d_in[1],
                                         (const float*)d_in[2],
                                         (const float*)d_in[3], wf, nW / 4);

    // fused QKV projection: [8192, 3072] = x @ [Wq;Wk;Wv]^T, fp16 out (NT)
    hgemm<<<dim3(3 * Dsz / BNT, BT / 128, 1), 256, SMEMB>>>(
        xf, wf, qkv, Dsz, Dsz, Dsz, 3 * Dsz, 0, 1, 0, 0, 0, 0);

    const h16* qf = qkv;
    const h16* kf = qkv + Dsz;
    const h16* vf = qkv + 2 * Dsz;

    // S = Q @ K^T (NT, exact lower-triangular 128x256 tile grid, fp16 out)
    int ntiles = 0;
    for (int r = 0; r < Tsz / 128; r++) ntiles += r / 2 + 1;   // 72
    hgemm<<<dim3(ntiles, 1, Bsz), 256, SMEMB>>>(
        qf, kf, s, Dsz, 3 * Dsz, 3 * Dsz, Tsz, 1, 1, 0,
        (long long)Tsz * 3 * Dsz, (long long)Tsz * 3 * Dsz,
        (long long)Tsz * Tsz);

    // causal softmax (fp16 S) -> P fp16 (tail zero-filled to 128 boundary)
    softmax_pf<<<dim3(Tsz, Bsz), 256>>>(s, pf);

    // O = P @ V (NN: V read in place from qkv, K clipped to row0+128)
    hgemm<<<dim3(Dsz / BNT, Tsz / 128, Bsz), 256, SMEMB>>>(
        pf, vf, out, Tsz, Tsz, 3 * Dsz, Dsz, 2, 0, 1,
        (long long)Tsz * Tsz, (long long)Tsz * 3 * Dsz,
        (long long)Tsz * Dsz);
}

// round 9
// speedup vs baseline: 1.1645x; 1.1645x over previous
#include <cuda_runtime.h>
#include <cuda_fp16.h>
#include <stdint.h>
#include <math.h>

#define Bsz 4
#define Tsz 2048
#define Dsz 1024
#define BT  (Bsz * Tsz)

typedef __half h16;

// ---------------- scratch (__device__ globals; allocation-free rule) -------
__device__ __align__(16) h16 g_s[(size_t)Bsz * Tsz * Tsz];   // fp16 scores
__device__ __align__(16) h16 g_xf[(size_t)BT * Dsz];
__device__ __align__(16) h16 g_wqt[(size_t)Dsz * Dsz];       // Wq^T fp16
__device__ __align__(16) h16 g_wk[(size_t)Dsz * Dsz];
__device__ __align__(16) h16 g_wv[(size_t)Dsz * Dsz];
__device__ __align__(16) h16 g_m[(size_t)Dsz * Dsz];         // M = Wq^T Wk
__device__ __align__(16) h16 g_am[(size_t)BT * Dsz];         // A = x @ M
__device__ __align__(16) h16 g_vp[(size_t)BT * Dsz];         // V = x @ Wv^T
__device__ __align__(16) h16 g_pf[(size_t)Bsz * Tsz * Tsz];

// ---------------- low-level helpers (plain sm_80-era PTX only) --------------
__device__ __forceinline__ uint32_t smem_u32(const void* p) {
    uint32_t a;
    asm("{ .reg .u64 t; cvta.to.shared.u64 t, %1; cvt.u32.u64 %0, t; }"
        : "=r"(a) : "l"(p));
    return a;
}

#define CP_ASYNC16(dst, src) \
    asm volatile("cp.async.cg.shared.global [%0], [%1], 16;" \
                 :: "r"(dst), "l"(src))
#define CP_COMMIT() asm volatile("cp.async.commit_group;")
#define CP_WAIT1()  asm volatile("cp.async.wait_group 1;")

__device__ __forceinline__ void ldsm4(uint32_t& r0, uint32_t& r1,
                                      uint32_t& r2, uint32_t& r3,
                                      uint32_t addr) {
    asm volatile("ldmatrix.sync.aligned.m8n8.x4.shared.b16 {%0,%1,%2,%3}, [%4];"
                 : "=r"(r0), "=r"(r1), "=r"(r2), "=r"(r3) : "r"(addr));
}

__device__ __forceinline__ void ldsm4t(uint32_t& r0, uint32_t& r1,
                                       uint32_t& r2, uint32_t& r3,
                                       uint32_t addr) {
    asm volatile(
        "ldmatrix.sync.aligned.m8n8.x4.trans.shared.b16 {%0,%1,%2,%3}, [%4];"
        : "=r"(r0), "=r"(r1), "=r"(r2), "=r"(r3) : "r"(addr));
}

__device__ __forceinline__ void mma16816(float* d, const uint32_t* a,
                                         const uint32_t* b) {
    asm volatile(
        "mma.sync.aligned.m16n8k16.row.col.f32.f16.f16.f32 "
        "{%0,%1,%2,%3}, {%4,%5,%6,%7}, {%8,%9}, {%0,%1,%2,%3};"
        : "+f"(d[0]), "+f"(d[1]), "+f"(d[2]), "+f"(d[3])
        : "r"(a[0]), "r"(a[1]), "r"(a[2]), "r"(a[3]), "r"(b[0]), "r"(b[1]));
}

// ---------------- HMMA GEMM (Round-7 proven config) --------------------------
// C[M,N] = A[M,K] * op(B).  bnn=0: B is [N,K] (NT).  bnn=1: B is [K,N] (NN).
// fp16 operands, fp32 accumulate. lda/ldb/ldc row strides (elements).
// mode 0: full grid.
// mode 1: blockIdx.x is a linear lower-triangular tile index (S-GEMM).
// mode 2: kend = row0+128, heavy rows first (PV GEMM).
// ofp16: write C as fp16 (else fp32).
#define KC     64
#define ROWB   144               // NT tile: 128B data + 16B pad per row
#define ROWBB  272               // NN B tile: 256B data + 16B pad per k-row
#define MATB   (128 * ROWB)      // 18432 B
#define STGB   (2 * MATB)        // A tile + B tile (NN B: 64*272=17408 <= MATB)
#define NSTG   3
#define SMEMB  (NSTG * STGB)     // 110592 B

__global__ void __launch_bounds__(256, 2) hgemm(
    const h16* __restrict__ Af, const h16* __restrict__ Bf,
    void* __restrict__ Cv, int K, int lda, int ldb, int ldc,
    int mode, int ofp16, int bnn, long long sA, long long sB, long long sC)
{
    const int bz = blockIdx.z;
    Af += (size_t)bz * sA;
    Bf += (size_t)bz * sB;

    int row0, col0;
    if (mode == 1) {
        // triangular decode: t -> (r, c), r >= c
        const int t = blockIdx.x;
        int r = (int)((__fsqrt_rn(8.f * (float)t + 1.f) - 1.f) * 0.5f);
        while ((r + 1) * (r + 2) / 2 <= t) r++;
        while (r * (r + 1) / 2 > t) r--;
        row0 = r * 128;
        col0 = (t - r * (r + 1) / 2) * 128;
    } else if (mode == 2) {
        const int by = (int)gridDim.y - 1 - (int)blockIdx.y;  // heavy first
        row0 = by * 128;
        col0 = blockIdx.x * 128;
    } else {
        row0 = blockIdx.y * 128;
        col0 = blockIdx.x * 128;
    }
    const int kend = (mode == 2) ? (row0 + 128) : K;
    const int nc = kend / KC;           // >= 2 always

    extern __shared__ char smc[];
    const uint32_t smb = smem_u32(smc);
    const int tid  = threadIdx.x;
    const int lane = tid & 31;
    const int wid  = tid >> 5;
    const int m0 = (wid & 1) * 64;      // warp tile 64x32, warps 2x4
    const int n0 = (wid >> 1) * 32;

    float acc[4][4][4];
#pragma unroll
    for (int i = 0; i < 4; i++)
#pragma unroll
        for (int j = 0; j < 4; j++)
#pragma unroll
            for (int q = 0; q < 4; q++) acc[i][j][q] = 0.f;

    const int lch  = tid & 7;      // NT: 16B chunk within 128B row
    const int lr0  = tid >> 3;     // 0..31
    const int lch2 = tid & 15;     // NN B: 16B chunk within 256B row
    const int lr2  = tid >> 4;     // 0..15

    auto do_load = [&](int st, int k0) {
        const uint32_t sb = smb + (uint32_t)st * STGB;
        const h16* pA = Af + (size_t)row0 * lda + k0;
#pragma unroll
        for (int j = 0; j < 4; j++) {
            const int row = lr0 + j * 32;
            CP_ASYNC16(sb + (uint32_t)(row * ROWB + lch * 16),
                       pA + (size_t)row * lda + lch * 8);
        }
        if (!bnn) {
            const h16* pB = Bf + (size_t)col0 * ldb + k0;
#pragma unroll
            for (int j = 0; j < 4; j++) {
                const int row = lr0 + j * 32;
                CP_ASYNC16(sb + MATB + (uint32_t)(row * ROWB + lch * 16),
                           pB + (size_t)row * ldb + lch * 8);
            }
        } else {
            const h16* pB = Bf + (size_t)k0 * ldb + col0;
#pragma unroll
            for (int j = 0; j < 4; j++) {
                const int row = lr2 + j * 16;     // k-row 0..63
                CP_ASYNC16(sb + MATB + (uint32_t)(row * ROWBB + lch2 * 16),
                           pB + (size_t)row * ldb + lch2 * 8);
            }
        }
    };

    do_load(0, 0);
    CP_COMMIT();
    do_load(1, KC);
    CP_COMMIT();

    for (int c = 0; c < nc; c++) {
        CP_WAIT1();                      // stage c resident
        __syncthreads();                 // all warps done with stage (c+2)%3
        if (c + 2 < nc) do_load((c + 2) % NSTG, (c + 2) * KC);
        CP_COMMIT();

        const uint32_t base = smb + (uint32_t)(c % NSTG) * STGB;
#pragma unroll
        for (int kk = 0; kk < 4; kk++) {          // four k16 steps per KC=64
            uint32_t a[4][4];
#pragma unroll
            for (int mi = 0; mi < 4; mi++) {
                const uint32_t ad = base +
                    (uint32_t)((m0 + mi * 16 + (lane & 15)) * ROWB +
                               (kk * 2 + (lane >> 4)) * 16);
                ldsm4(a[mi][0], a[mi][1], a[mi][2], a[mi][3], ad);
            }
            uint32_t bb[4][2];
            if (!bnn) {
#pragma unroll
                for (int np = 0; np < 2; np++) {  // [N,K]: non-trans ldsm
                    const int rb = n0 + np * 16 + (lane & 7) + ((lane >> 4) << 3);
                    const int ch = kk * 2 + ((lane >> 3) & 1);
                    const uint32_t ad = base + MATB +
                        (uint32_t)(rb * ROWB + ch * 16);
                    ldsm4(bb[np*2][0], bb[np*2][1],
                          bb[np*2+1][0], bb[np*2+1][1], ad);
                }
            } else {
#pragma unroll
                for (int g = 0; g < 2; g++) {     // [K,N]: trans ldsm
                    const uint32_t ad = base + MATB +
                        (uint32_t)((kk * 16 + (lane & 15)) * ROWBB +
                                   (n0 + g * 16 + ((lane >> 4) << 3)) * 2);
                    ldsm4t(bb[g*2][0], bb[g*2][1],
                           bb[g*2+1][0], bb[g*2+1][1], ad);
                }
            }
#pragma unroll
            for (int mi = 0; mi < 4; mi++)
#pragma unroll
                for (int ni = 0; ni < 4; ni++)
                    mma16816(acc[mi][ni], a[mi], bb[ni]);
        }
    }

    // epilogue
    const int er = lane >> 2;
    const int ec = (lane & 3) * 2;
    if (!ofp16) {
        float* C = (float*)Cv + (size_t)bz * sC;
#pragma unroll
        for (int mi = 0; mi < 4; mi++) {
            const int r = row0 + m0 + mi * 16 + er;
#pragma unroll
            for (int ni = 0; ni < 4; ni++) {
                const int cc = col0 + n0 + ni * 8 + ec;
                *(float2*)&C[(size_t)r * ldc + cc] =
                    make_float2(acc[mi][ni][0], acc[mi][ni][1]);
                *(float2*)&C[(size_t)(r + 8) * ldc + cc] =
                    make_float2(acc[mi][ni][2], acc[mi][ni][3]);
            }
        }
    } else {
        h16* C = (h16*)Cv + (size_t)bz * sC;
#pragma unroll
        for (int mi = 0; mi < 4; mi++) {
            const int r = row0 + m0 + mi * 16 + er;
#pragma unroll
            for (int ni = 0; ni < 4; ni++) {
                const int cc = col0 + n0 + ni * 8 + ec;
                __half2 h0 = __floats2half2_rn(acc[mi][ni][0], acc[mi][ni][1]);
                __half2 h1 = __floats2half2_rn(acc[mi][ni][2], acc[mi][ni][3]);
                *(__half2*)&C[(size_t)r * ldc + cc] = h0;
                *(__half2*)&C[(size_t)(r + 8) * ldc + cc] = h1;
            }
        }
    }
}

// ---------------- conversions ------------------------------------------------
__global__ void __launch_bounds__(256) conv_single(
    const float* __restrict__ in, h16* __restrict__ o, int n4)
{
    int i = blockIdx.x * 256 + threadIdx.x;
    if (i >= n4) return;
    float4 v = ((const float4*)in)[i];
    __half2 p0 = __floats2half2_rn(v.x, v.y);
    __half2 p1 = __floats2half2_rn(v.z, v.w);
    uint2 u;
    u.x = *(uint32_t*)&p0;
    u.y = *(uint32_t*)&p1;
    ((uint2*)o)[i] = u;
}

// Wq [o,d] fp32 -> Wq^T [d,o] fp16
__global__ void __launch_bounds__(256) conv_wt(
    const float* __restrict__ w, h16* __restrict__ o)
{
    __shared__ float tile[32][33];
    const int d0 = blockIdx.x * 32;
    const int o0 = blockIdx.y * 32;
    const int tx = threadIdx.x & 31, ty = threadIdx.x >> 5;
#pragma unroll
    for (int j = ty; j < 32; j += 8)
        tile[j][tx] = w[(size_t)(o0 + j) * Dsz + d0 + tx];   // w[o][d]
    __syncthreads();
#pragma unroll
    for (int j = ty; j < 32; j += 8)
        o[(size_t)(d0 + j) * Dsz + o0 + tx] = __float2half_rn(tile[tx][j]);
}

// ---------------- causal softmax over fp16 S -> fp16 P ----------------------
__device__ __forceinline__ float warp_max_f(float v) {
#pragma unroll
    for (int o = 16; o; o >>= 1) v = fmaxf(v, __shfl_xor_sync(0xffffffffu, v, o));
    return v;
}
__device__ __forceinline__ float warp_sum_f(float v) {
#pragma unroll
    for (int o = 16; o; o >>= 1) v += __shfl_xor_sync(0xffffffffu, v, o);
    return v;
}

__global__ void __launch_bounds__(256) softmax_pf(
    const h16* __restrict__ S, h16* __restrict__ pf)
{
    __shared__ float es[Tsz];
    __shared__ float red[8];
    const int b = blockIdx.y;
    const int r = blockIdx.x;
    const h16* row = S + ((size_t)b * Tsz + r) * Tsz;
    h16* pr = pf + ((size_t)b * Tsz + r) * Tsz;
    const int blk_end = ((r >> 7) + 1) << 7;   // padded to 128
    const int n8 = blk_end >> 3;
    const float scale = 0.03125f;              // 1/sqrt(1024)
    const int tid = threadIdx.x;

    float m = -INFINITY;
    for (int i8 = tid; i8 < n8; i8 += 256) {
        uint4 u = ((const uint4*)row)[i8];
        float2 f0 = __half22float2(*(__half2*)&u.x);
        float2 f1 = __half22float2(*(__half2*)&u.y);
        float2 f2 = __half22float2(*(__half2*)&u.z);
        float2 f3 = __half22float2(*(__half2*)&u.w);
        const int base = i8 << 3;
        if (base + 7 <= r) {
            m = fmaxf(m, fmaxf(fmaxf(f0.x, f0.y), fmaxf(f1.x, f1.y)));
            m = fmaxf(m, fmaxf(fmaxf(f2.x, f2.y), fmaxf(f3.x, f3.y)));
        } else {
            float vv[8] = {f0.x, f0.y, f1.x, f1.y, f2.x, f2.y, f3.x, f3.y};
#pragma unroll
            for (int j = 0; j < 8; j++)
                if (base + j <= r) m = fmaxf(m, vv[j]);
        }
    }
    m = warp_max_f(m);
    if ((tid & 31) == 0) red[tid >> 5] = m;
    __syncthreads();
    m = red[0];
#pragma unroll
    for (int i = 1; i < 8; i++) m = fmaxf(m, red[i]);
    __syncthreads();

    float ssum = 0.f;
    for (int i8 = tid; i8 < n8; i8 += 256) {
        uint4 u = ((const uint4*)row)[i8];
        float2 f0 = __half22float2(*(__half2*)&u.x);
        float2 f1 = __half22float2(*(__half2*)&u.y);
        float2 f2 = __half22float2(*(__half2*)&u.z);
        float2 f3 = __half22float2(*(__half2*)&u.w);
        float vv[8] = {f0.x, f0.y, f1.x, f1.y, f2.x, f2.y, f3.x, f3.y};
        const int base = i8 << 3;
        float e[8];
#pragma unroll
        for (int j = 0; j < 8; j++) {
            e[j] = (base + j <= r) ? __expf((vv[j] - m) * scale) : 0.f;
            ssum += e[j];
        }
        ((float4*)es)[i8 * 2 + 0] = make_float4(e[0], e[1], e[2], e[3]);
        ((float4*)es)[i8 * 2 + 1] = make_float4(e[4], e[5], e[6], e[7]);
    }
    ssum = warp_sum_f(ssum);
    if ((tid & 31) == 0) red[tid >> 5] = ssum;
    __syncthreads();
    ssum = 0.f;
#pragma unroll
    for (int i = 0; i < 8; i++) ssum += red[i];
    const float inv = 1.f / ssum;
    __syncthreads();

    for (int i8 = tid; i8 < n8; i8 += 256) {
        float4 e0 = ((const float4*)es)[i8 * 2 + 0];
        float4 e1 = ((const float4*)es)[i8 * 2 + 1];
        __half2 h0 = __floats2half2_rn(e0.x * inv, e0.y * inv);
        __half2 h1 = __floats2half2_rn(e0.z * inv, e0.w * inv);
        __half2 h2 = __floats2half2_rn(e1.x * inv, e1.y * inv);
        __half2 h3 = __floats2half2_rn(e1.z * inv, e1.w * inv);
        uint4 u;
        u.x = *(uint32_t*)&h0;
        u.y = *(uint32_t*)&h1;
        u.z = *(uint32_t*)&h2;
        u.w = *(uint32_t*)&h3;
        ((uint4*)pr)[i8] = u;
    }
}

// ---------------- launch ------------------------------------------------------
extern "C" void kernel_launch(void* const* d_in, const int* in_sizes, int n_in,
                              void* d_out, int out_size)
{
    (void)in_sizes; (void)n_in; (void)out_size;
    const float* x  = (const float*)d_in[0];
    const float* Wq = (const float*)d_in[1];
    const float* Wk = (const float*)d_in[2];
    const float* Wv = (const float*)d_in[3];
    float* out = (float*)d_out;

    h16 *s, *xf, *wqt, *wk, *wv, *mm, *am, *vp, *pf;
    cudaGetSymbolAddress((void**)&s,   g_s);
    cudaGetSymbolAddress((void**)&xf,  g_xf);
    cudaGetSymbolAddress((void**)&wqt, g_wqt);
    cudaGetSymbolAddress((void**)&wk,  g_wk);
    cudaGetSymbolAddress((void**)&wv,  g_wv);
    cudaGetSymbolAddress((void**)&mm,  g_m);
    cudaGetSymbolAddress((void**)&am,  g_am);
    cudaGetSymbolAddress((void**)&vp,  g_vp);
    cudaGetSymbolAddress((void**)&pf,  g_pf);

    cudaFuncSetAttribute(hgemm, cudaFuncAttributeMaxDynamicSharedMemorySize,
                         SMEMB);

    const int nX = BT * Dsz;    // 8M
    const int nW = Dsz * Dsz;   // 1M

    // conversions
    conv_single<<<nX / 4 / 256, 256>>>(x, xf, nX / 4);
    conv_single<<<nW / 4 / 256, 256>>>(Wk, wk, nW / 4);
    conv_single<<<nW / 4 / 256, 256>>>(Wv, wv, nW / 4);
    conv_wt<<<dim3(Dsz / 32, Dsz / 32), 256>>>(Wq, wqt);

    // M = Wq^T @ Wk   [1024,1024] (NN: A=WqT, B=Wk[o,e]), fp16 out
    hgemm<<<dim3(Dsz / 128, Dsz / 128, 1), 256, SMEMB>>>(
        wqt, wk, mm, Dsz, Dsz, Dsz, Dsz, 0, 1, 1, 0, 0, 0);

    // A = x @ M       [8192,1024] (NN: B=M[d,e]), fp16 out
    hgemm<<<dim3(Dsz / 128, BT / 128, 1), 256, SMEMB>>>(
        xf, mm, am, Dsz, Dsz, Dsz, Dsz, 0, 1, 1, 0, 0, 0);

    // V = x @ Wv^T    [8192,1024] (NT), fp16 out
    hgemm<<<dim3(Dsz / 128, BT / 128, 1), 256, SMEMB>>>(
        xf, wv, vp, Dsz, Dsz, Dsz, Dsz, 0, 1, 0, 0, 0, 0);

    // S = A @ x^T per batch (NT, triangular tile grid), fp16 out
    const int ntiles = (Tsz / 128) * (Tsz / 128 + 1) / 2;   // 136
    hgemm<<<dim3(ntiles, 1, Bsz), 256, SMEMB>>>(
        am, xf, s, Dsz, Dsz, Dsz, Tsz, 1, 1, 0,
        (long long)Tsz * Dsz, (long long)Tsz * Dsz,
        (long long)Tsz * Tsz);

    // causal softmax (fp16 S) -> P fp16 (tail zero-filled to 128 boundary)
    softmax_pf<<<dim3(Tsz, Bsz), 256>>>(s, pf);

    // O = P @ V (NN: B=V[t,d], K clipped to row0+128), fp32 out
    hgemm<<<dim3(Dsz / 128, Tsz / 128, Bsz), 256, SMEMB>>>(
        pf, vp, out, Tsz, Tsz, Dsz, Dsz, 2, 0, 1,
        (long long)Tsz * Tsz, (long long)Tsz * Dsz,
        (long long)Tsz * Dsz);
}

// round 10
// speedup vs baseline: 1.2312x; 1.0573x over previous
#include <cuda_runtime.h>
#include <cuda_fp16.h>
#include <stdint.h>
#include <math.h>

#define Bsz 4
#define Tsz 2048
#define Dsz 1024
#define BT  (Bsz * Tsz)

typedef __half h16;

// ---------------- scratch (__device__ globals; allocation-free rule) -------
__device__ __align__(16) h16 g_s[(size_t)Bsz * Tsz * Tsz];   // fp16 scores
__device__ __align__(16) h16 g_xf[(size_t)BT * Dsz];
__device__ __align__(16) h16 g_wqt[(size_t)Dsz * Dsz];       // Wq^T fp16
__device__ __align__(16) h16 g_wk[(size_t)Dsz * Dsz];        // Wk fp16
__device__ __align__(16) h16 g_bc[(size_t)Dsz * 2 * Dsz];    // B' = [M | Wv^T]
__device__ __align__(16) h16 g_av[(size_t)BT * 2 * Dsz];     // [A | V] fused out
__device__ __align__(16) h16 g_pf[(size_t)Bsz * Tsz * Tsz];

// ---------------- low-level helpers (plain sm_80-era PTX only) --------------
__device__ __forceinline__ uint32_t smem_u32(const void* p) {
    uint32_t a;
    asm("{ .reg .u64 t; cvta.to.shared.u64 t, %1; cvt.u32.u64 %0, t; }"
        : "=r"(a) : "l"(p));
    return a;
}

#define CP_ASYNC16(dst, src) \
    asm volatile("cp.async.cg.shared.global [%0], [%1], 16;" \
                 :: "r"(dst), "l"(src))
#define CP_COMMIT() asm volatile("cp.async.commit_group;")
#define CP_WAIT1()  asm volatile("cp.async.wait_group 1;")

__device__ __forceinline__ void ldsm4(uint32_t& r0, uint32_t& r1,
                                      uint32_t& r2, uint32_t& r3,
                                      uint32_t addr) {
    asm volatile("ldmatrix.sync.aligned.m8n8.x4.shared.b16 {%0,%1,%2,%3}, [%4];"
                 : "=r"(r0), "=r"(r1), "=r"(r2), "=r"(r3) : "r"(addr));
}

__device__ __forceinline__ void ldsm4t(uint32_t& r0, uint32_t& r1,
                                       uint32_t& r2, uint32_t& r3,
                                       uint32_t addr) {
    asm volatile(
        "ldmatrix.sync.aligned.m8n8.x4.trans.shared.b16 {%0,%1,%2,%3}, [%4];"
        : "=r"(r0), "=r"(r1), "=r"(r2), "=r"(r3) : "r"(addr));
}

__device__ __forceinline__ void mma16816(float* d, const uint32_t* a,
                                         const uint32_t* b) {
    asm volatile(
        "mma.sync.aligned.m16n8k16.row.col.f32.f16.f16.f32 "
        "{%0,%1,%2,%3}, {%4,%5,%6,%7}, {%8,%9}, {%0,%1,%2,%3};"
        : "+f"(d[0]), "+f"(d[1]), "+f"(d[2]), "+f"(d[3])
        : "r"(a[0]), "r"(a[1]), "r"(a[2]), "r"(a[3]), "r"(b[0]), "r"(b[1]));
}

// ---------------- HMMA GEMM (proven at-ceiling config) -----------------------
// C[M,N] = A[M,K] * op(B).  bnn=0: B is [N,K] (NT).  bnn=1: B is [K,N] (NN).
// fp16 operands, fp32 accumulate. lda/ldb/ldc row strides (elements).
// mode 0: full grid.
// mode 1: blockIdx.x is a linear lower-triangular tile index (S-GEMM).
// mode 2: kend = row0+128, heavy rows first (PV GEMM).
// ofp16: write C as fp16 (else fp32).
#define KC     64
#define ROWB   144               // NT tile: 128B data + 16B pad per row
#define ROWBB  272               // NN B tile: 256B data + 16B pad per k-row
#define MATB   (128 * ROWB)      // 18432 B
#define STGB   (2 * MATB)        // A tile + B tile (NN B: 64*272=17408 <= MATB)
#define NSTG   3
#define SMEMB  (NSTG * STGB)     // 110592 B

__global__ void __launch_bounds__(256, 2) hgemm(
    const h16* __restrict__ Af, const h16* __restrict__ Bf,
    void* __restrict__ Cv, int K, int lda, int ldb, int ldc,
    int mode, int ofp16, int bnn, long long sA, long long sB, long long sC)
{
    const int bz = blockIdx.z;
    Af += (size_t)bz * sA;
    Bf += (size_t)bz * sB;

    int row0, col0;
    if (mode == 1) {
        // triangular decode: t -> (r, c), r >= c
        const int t = blockIdx.x;
        int r = (int)((__fsqrt_rn(8.f * (float)t + 1.f) - 1.f) * 0.5f);
        while ((r + 1) * (r + 2) / 2 <= t) r++;
        while (r * (r + 1) / 2 > t) r--;
        row0 = r * 128;
        col0 = (t - r * (r + 1) / 2) * 128;
    } else if (mode == 2) {
        const int by = (int)gridDim.y - 1 - (int)blockIdx.y;  // heavy first
        row0 = by * 128;
        col0 = blockIdx.x * 128;
    } else {
        row0 = blockIdx.y * 128;
        col0 = blockIdx.x * 128;
    }
    const int kend = (mode == 2) ? (row0 + 128) : K;
    const int nc = kend / KC;           // >= 2 always

    extern __shared__ char smc[];
    const uint32_t smb = smem_u32(smc);
    const int tid  = threadIdx.x;
    const int lane = tid & 31;
    const int wid  = tid >> 5;
    const int m0 = (wid & 1) * 64;      // warp tile 64x32, warps 2x4
    const int n0 = (wid >> 1) * 32;

    float acc[4][4][4];
#pragma unroll
    for (int i = 0; i < 4; i++)
#pragma unroll
        for (int j = 0; j < 4; j++)
#pragma unroll
            for (int q = 0; q < 4; q++) acc[i][j][q] = 0.f;

    const int lch  = tid & 7;      // NT: 16B chunk within 128B row
    const int lr0  = tid >> 3;     // 0..31
    const int lch2 = tid & 15;     // NN B: 16B chunk within 256B row
    const int lr2  = tid >> 4;     // 0..15

    auto do_load = [&](int st, int k0) {
        const uint32_t sb = smb + (uint32_t)st * STGB;
        const h16* pA = Af + (size_t)row0 * lda + k0;
#pragma unroll
        for (int j = 0; j < 4; j++) {
            const int row = lr0 + j * 32;
            CP_ASYNC16(sb + (uint32_t)(row * ROWB + lch * 16),
                       pA + (size_t)row * lda + lch * 8);
        }
        if (!bnn) {
            const h16* pB = Bf + (size_t)col0 * ldb + k0;
#pragma unroll
            for (int j = 0; j < 4; j++) {
                const int row = lr0 + j * 32;
                CP_ASYNC16(sb + MATB + (uint32_t)(row * ROWB + lch * 16),
                           pB + (size_t)row * ldb + lch * 8);
            }
        } else {
            const h16* pB = Bf + (size_t)k0 * ldb + col0;
#pragma unroll
            for (int j = 0; j < 4; j++) {
                const int row = lr2 + j * 16;     // k-row 0..63
                CP_ASYNC16(sb + MATB + (uint32_t)(row * ROWBB + lch2 * 16),
                           pB + (size_t)row * ldb + lch2 * 8);
            }
        }
    };

    do_load(0, 0);
    CP_COMMIT();
    do_load(1, KC);
    CP_COMMIT();

    for (int c = 0; c < nc; c++) {
        CP_WAIT1();                      // stage c resident
        __syncthreads();                 // all warps done with stage (c+2)%3
        if (c + 2 < nc) do_load((c + 2) % NSTG, (c + 2) * KC);
        CP_COMMIT();

        const uint32_t base = smb + (uint32_t)(c % NSTG) * STGB;
#pragma unroll
        for (int kk = 0; kk < 4; kk++) {          // four k16 steps per KC=64
            uint32_t a[4][4];
#pragma unroll
            for (int mi = 0; mi < 4; mi++) {
                const uint32_t ad = base +
                    (uint32_t)((m0 + mi * 16 + (lane & 15)) * ROWB +
                               (kk * 2 + (lane >> 4)) * 16);
                ldsm4(a[mi][0], a[mi][1], a[mi][2], a[mi][3], ad);
            }
            uint32_t bb[4][2];
            if (!bnn) {
#pragma unroll
                for (int np = 0; np < 2; np++) {  // [N,K]: non-trans ldsm
                    const int rb = n0 + np * 16 + (lane & 7) + ((lane >> 4) << 3);
                    const int ch = kk * 2 + ((lane >> 3) & 1);
                    const uint32_t ad = base + MATB +
                        (uint32_t)(rb * ROWB + ch * 16);
                    ldsm4(bb[np*2][0], bb[np*2][1],
                          bb[np*2+1][0], bb[np*2+1][1], ad);
                }
            } else {
#pragma unroll
                for (int g = 0; g < 2; g++) {     // [K,N]: trans ldsm
                    const uint32_t ad = base + MATB +
                        (uint32_t)((kk * 16 + (lane & 15)) * ROWBB +
                                   (n0 + g * 16 + ((lane >> 4) << 3)) * 2);
                    ldsm4t(bb[g*2][0], bb[g*2][1],
                           bb[g*2+1][0], bb[g*2+1][1], ad);
                }
            }
#pragma unroll
            for (int mi = 0; mi < 4; mi++)
#pragma unroll
                for (int ni = 0; ni < 4; ni++)
                    mma16816(acc[mi][ni], a[mi], bb[ni]);
        }
    }

    // epilogue
    const int er = lane >> 2;
    const int ec = (lane & 3) * 2;
    if (!ofp16) {
        float* C = (float*)Cv + (size_t)bz * sC;
#pragma unroll
        for (int mi = 0; mi < 4; mi++) {
            const int r = row0 + m0 + mi * 16 + er;
#pragma unroll
            for (int ni = 0; ni < 4; ni++) {
                const int cc = col0 + n0 + ni * 8 + ec;
                *(float2*)&C[(size_t)r * ldc + cc] =
                    make_float2(acc[mi][ni][0], acc[mi][ni][1]);
                *(float2*)&C[(size_t)(r + 8) * ldc + cc] =
                    make_float2(acc[mi][ni][2], acc[mi][ni][3]);
            }
        }
    } else {
        h16* C = (h16*)Cv + (size_t)bz * sC;
#pragma unroll
        for (int mi = 0; mi < 4; mi++) {
            const int r = row0 + m0 + mi * 16 + er;
#pragma unroll
            for (int ni = 0; ni < 4; ni++) {
                const int cc = col0 + n0 + ni * 8 + ec;
                __half2 h0 = __floats2half2_rn(acc[mi][ni][0], acc[mi][ni][1]);
                __half2 h1 = __floats2half2_rn(acc[mi][ni][2], acc[mi][ni][3]);
                *(__half2*)&C[(size_t)r * ldc + cc] = h0;
                *(__half2*)&C[(size_t)(r + 8) * ldc + cc] = h1;
            }
        }
    }
}

// ---------------- conversions ------------------------------------------------
__global__ void __launch_bounds__(256) conv_single(
    const float* __restrict__ in, h16* __restrict__ o, int n4)
{
    int i = blockIdx.x * 256 + threadIdx.x;
    if (i >= n4) return;
    float4 v = ((const float4*)in)[i];
    __half2 p0 = __floats2half2_rn(v.x, v.y);
    __half2 p1 = __floats2half2_rn(v.z, v.w);
    uint2 u;
    u.x = *(uint32_t*)&p0;
    u.y = *(uint32_t*)&p1;
    ((uint2*)o)[i] = u;
}

// W [o,d] fp32 -> W^T [d,o] fp16 with output row stride ldo
__global__ void __launch_bounds__(256) conv_wt(
    const float* __restrict__ w, h16* __restrict__ o, int ldo)
{
    __shared__ float tile[32][33];
    const int d0 = blockIdx.x * 32;
    const int o0 = blockIdx.y * 32;
    const int tx = threadIdx.x & 31, ty = threadIdx.x >> 5;
#pragma unroll
    for (int j = ty; j < 32; j += 8)
        tile[j][tx] = w[(size_t)(o0 + j) * Dsz + d0 + tx];   // w[o][d]
    __syncthreads();
#pragma unroll
    for (int j = ty; j < 32; j += 8)
        o[(size_t)(d0 + j) * ldo + o0 + tx] = __float2half_rn(tile[tx][j]);
}

// ---------------- causal softmax over fp16 S -> fp16 P (single gmem read) ---
__device__ __forceinline__ float warp_max_f(float v) {
#pragma unroll
    for (int o = 16; o; o >>= 1) v = fmaxf(v, __shfl_xor_sync(0xffffffffu, v, o));
    return v;
}
__device__ __forceinline__ float warp_sum_f(float v) {
#pragma unroll
    for (int o = 16; o; o >>= 1) v += __shfl_xor_sync(0xffffffffu, v, o);
    return v;
}

__global__ void __launch_bounds__(256) softmax_pf(
    const h16* __restrict__ S, h16* __restrict__ pf)
{
    __shared__ float es[Tsz];
    __shared__ float red[8];
    const int b = blockIdx.y;
    const int r = blockIdx.x;
    const h16* row = S + ((size_t)b * Tsz + r) * Tsz;
    h16* pr = pf + ((size_t)b * Tsz + r) * Tsz;
    const int blk_end = ((r >> 7) + 1) << 7;   // padded to 128
    const int n8 = blk_end >> 3;
    const float scale = 0.03125f;              // 1/sqrt(1024)
    const int tid = threadIdx.x;

    // pass 1: ONE gmem read -> raw floats into smem + masked max
    float m = -INFINITY;
    for (int i8 = tid; i8 < n8; i8 += 256) {
        uint4 u = ((const uint4*)row)[i8];
        float2 f0 = __half22float2(*(__half2*)&u.x);
        float2 f1 = __half22float2(*(__half2*)&u.y);
        float2 f2 = __half22float2(*(__half2*)&u.z);
        float2 f3 = __half22float2(*(__half2*)&u.w);
        ((float4*)es)[i8 * 2 + 0] = make_float4(f0.x, f0.y, f1.x, f1.y);
        ((float4*)es)[i8 * 2 + 1] = make_float4(f2.x, f2.y, f3.x, f3.y);
        const int base = i8 << 3;
        if (base + 7 <= r) {
            m = fmaxf(m, fmaxf(fmaxf(f0.x, f0.y), fmaxf(f1.x, f1.y)));
            m = fmaxf(m, fmaxf(fmaxf(f2.x, f2.y), fmaxf(f3.x, f3.y)));
        } else {
            float vv[8] = {f0.x, f0.y, f1.x, f1.y, f2.x, f2.y, f3.x, f3.y};
#pragma unroll
            for (int j = 0; j < 8; j++)
                if (base + j <= r) m = fmaxf(m, vv[j]);
        }
    }
    m = warp_max_f(m);
    if ((tid & 31) == 0) red[tid >> 5] = m;
    __syncthreads();
    m = red[0];
#pragma unroll
    for (int i = 1; i < 8; i++) m = fmaxf(m, red[i]);
    __syncthreads();

    // pass 2: smem -> masked exp in place + sum (same-thread element ownership)
    float ssum = 0.f;
    for (int i8 = tid; i8 < n8; i8 += 256) {
        float4 v0 = ((const float4*)es)[i8 * 2 + 0];
        float4 v1 = ((const float4*)es)[i8 * 2 + 1];
        float vv[8] = {v0.x, v0.y, v0.z, v0.w, v1.x, v1.y, v1.z, v1.w};
        const int base = i8 << 3;
        float e[8];
#pragma unroll
        for (int j = 0; j < 8; j++) {
            e[j] = (base + j <= r) ? __expf((vv[j] - m) * scale) : 0.f;
            ssum += e[j];
        }
        ((float4*)es)[i8 * 2 + 0] = make_float4(e[0], e[1], e[2], e[3]);
        ((float4*)es)[i8 * 2 + 1] = make_float4(e[4], e[5], e[6], e[7]);
    }
    ssum = warp_sum_f(ssum);
    if ((tid & 31) == 0) red[tid >> 5] = ssum;
    __syncthreads();
    ssum = 0.f;
#pragma unroll
    for (int i = 0; i < 8; i++) ssum += red[i];
    const float inv = 1.f / ssum;
    __syncthreads();

    // pass 3: normalize + write fp16 (tail zeros come for free)
    for (int i8 = tid; i8 < n8; i8 += 256) {
        float4 e0 = ((const float4*)es)[i8 * 2 + 0];
        float4 e1 = ((const float4*)es)[i8 * 2 + 1];
        __half2 h0 = __floats2half2_rn(e0.x * inv, e0.y * inv);
        __half2 h1 = __floats2half2_rn(e0.z * inv, e0.w * inv);
        __half2 h2 = __floats2half2_rn(e1.x * inv, e1.y * inv);
        __half2 h3 = __floats2half2_rn(e1.z * inv, e1.w * inv);
        uint4 u;
        u.x = *(uint32_t*)&h0;
        u.y = *(uint32_t*)&h1;
        u.z = *(uint32_t*)&h2;
        u.w = *(uint32_t*)&h3;
        ((uint4*)pr)[i8] = u;
    }
}

// ---------------- launch ------------------------------------------------------
extern "C" void kernel_launch(void* const* d_in, const int* in_sizes, int n_in,
                              void* d_out, int out_size)
{
    (void)in_sizes; (void)n_in; (void)out_size;
    const float* x  = (const float*)d_in[0];
    const float* Wq = (const float*)d_in[1];
    const float* Wk = (const float*)d_in[2];
    const float* Wv = (const float*)d_in[3];
    float* out = (float*)d_out;

    h16 *s, *xf, *wqt, *wk, *bc, *av, *pf;
    cudaGetSymbolAddress((void**)&s,   g_s);
    cudaGetSymbolAddress((void**)&xf,  g_xf);
    cudaGetSymbolAddress((void**)&wqt, g_wqt);
    cudaGetSymbolAddress((void**)&wk,  g_wk);
    cudaGetSymbolAddress((void**)&bc,  g_bc);
    cudaGetSymbolAddress((void**)&av,  g_av);
    cudaGetSymbolAddress((void**)&pf,  g_pf);

    cudaFuncSetAttribute(hgemm, cudaFuncAttributeMaxDynamicSharedMemorySize,
                         SMEMB);

    const int nX = BT * Dsz;    // 8M
    const int nW = Dsz * Dsz;   // 1M

    // conversions
    conv_single<<<nX / 4 / 256, 256>>>(x, xf, nX / 4);
    conv_single<<<nW / 4 / 256, 256>>>(Wk, wk, nW / 4);
    conv_wt<<<dim3(Dsz / 32, Dsz / 32), 256>>>(Wq, wqt, Dsz);
    conv_wt<<<dim3(Dsz / 32, Dsz / 32), 256>>>(Wv, bc + Dsz, 2 * Dsz);

    // M = Wq^T @ Wk -> B' cols [0,1024)   (NN, fp16 out, ldc=2048)
    hgemm<<<dim3(Dsz / 128, Dsz / 128, 1), 256, SMEMB>>>(
        wqt, wk, bc, Dsz, Dsz, Dsz, 2 * Dsz, 0, 1, 1, 0, 0, 0);

    // [A | V] = x @ B'   [8192, 2048] (NN, fp16 out)
    hgemm<<<dim3(2 * Dsz / 128, BT / 128, 1), 256, SMEMB>>>(
        xf, bc, av, Dsz, Dsz, 2 * Dsz, 2 * Dsz, 0, 1, 1, 0, 0, 0);

    const h16* am = av;             // A, row stride 2048
    const h16* vp = av + Dsz;       // V, row stride 2048

    // S = A @ x^T per batch (NT, triangular tile grid), fp16 out
    const int ntiles = (Tsz / 128) * (Tsz / 128 + 1) / 2;   // 136
    hgemm<<<dim3(ntiles, 1, Bsz), 256, SMEMB>>>(
        am, xf, s, Dsz, 2 * Dsz, Dsz, Tsz, 1, 1, 0,
        (long long)Tsz * 2 * Dsz, (long long)Tsz * Dsz,
        (long long)Tsz * Tsz);

    // causal softmax (fp16 S) -> P fp16 (tail zero-filled to 128 boundary)
    softmax_pf<<<dim3(Tsz, Bsz), 256>>>(s, pf);

    // O = P @ V (NN: B=V rows stride 2048, K clipped to row0+128), fp32 out
    hgemm<<<dim3(Dsz / 128, Tsz / 128, Bsz), 256, SMEMB>>>(
        pf, vp, out, Tsz, Tsz, 2 * Dsz, Dsz, 2, 0, 1,
        (long long)Tsz * Tsz, (long long)Tsz * 2 * Dsz,
        (long long)Tsz * Dsz);
}

// round 11
// speedup vs baseline: 1.2534x; 1.0180x over previous
#include <cuda_runtime.h>
#include <cuda_fp16.h>
#include <stdint.h>
#include <math.h>

#define Bsz 4
#define Tsz 2048
#define Dsz 1024
#define BT  (Bsz * Tsz)

typedef __half h16;

// ---------------- scratch (__device__ globals; allocation-free rule) -------
__device__ __align__(16) h16 g_s[(size_t)Bsz * Tsz * Tsz];   // fp16 scores
__device__ __align__(16) h16 g_xf[(size_t)BT * Dsz];
__device__ __align__(16) h16 g_wqt[(size_t)Dsz * Dsz];       // Wq^T fp16
__device__ __align__(16) h16 g_wk[(size_t)Dsz * Dsz];        // Wk fp16
__device__ __align__(16) h16 g_bc[(size_t)Dsz * 2 * Dsz];    // B' = [M | Wv^T]
__device__ __align__(16) h16 g_av[(size_t)BT * 2 * Dsz];     // [A | V] fused out
__device__ __align__(16) h16 g_pf[(size_t)Bsz * Tsz * Tsz];

// ---------------- low-level helpers (plain sm_80-era PTX only) --------------
__device__ __forceinline__ uint32_t smem_u32(const void* p) {
    uint32_t a;
    asm("{ .reg .u64 t; cvta.to.shared.u64 t, %1; cvt.u32.u64 %0, t; }"
        : "=r"(a) : "l"(p));
    return a;
}

#define CP_ASYNC16(dst, src) \
    asm volatile("cp.async.cg.shared.global [%0], [%1], 16;" \
                 :: "r"(dst), "l"(src))
#define CP_COMMIT() asm volatile("cp.async.commit_group;")
#define CP_WAIT1()  asm volatile("cp.async.wait_group 1;")

__device__ __forceinline__ void ldsm4(uint32_t& r0, uint32_t& r1,
                                      uint32_t& r2, uint32_t& r3,
                                      uint32_t addr) {
    asm volatile("ldmatrix.sync.aligned.m8n8.x4.shared.b16 {%0,%1,%2,%3}, [%4];"
                 : "=r"(r0), "=r"(r1), "=r"(r2), "=r"(r3) : "r"(addr));
}

__device__ __forceinline__ void ldsm4t(uint32_t& r0, uint32_t& r1,
                                       uint32_t& r2, uint32_t& r3,
                                       uint32_t addr) {
    asm volatile(
        "ldmatrix.sync.aligned.m8n8.x4.trans.shared.b16 {%0,%1,%2,%3}, [%4];"
        : "=r"(r0), "=r"(r1), "=r"(r2), "=r"(r3) : "r"(addr));
}

__device__ __forceinline__ void mma16816(float* d, const uint32_t* a,
                                         const uint32_t* b) {
    asm volatile(
        "mma.sync.aligned.m16n8k16.row.col.f32.f16.f16.f32 "
        "{%0,%1,%2,%3}, {%4,%5,%6,%7}, {%8,%9}, {%0,%1,%2,%3};"
        : "+f"(d[0]), "+f"(d[1]), "+f"(d[2]), "+f"(d[3])
        : "r"(a[0]), "r"(a[1]), "r"(a[2]), "r"(a[3]), "r"(b[0]), "r"(b[1]));
}

// ---------------- HMMA GEMM (proven at-ceiling config) -----------------------
// C[M,N] = A[M,K] * op(B).  bnn=0: B is [N,K] (NT).  bnn=1: B is [K,N] (NN).
// mode 0: full grid.  mode 1: triangular tile index.  mode 2: kend=row0+128.
#define KC     64
#define ROWB   144
#define ROWBB  272
#define MATB   (128 * ROWB)
#define STGB   (2 * MATB)
#define NSTG   3
#define SMEMB  (NSTG * STGB)     // 110592 B

__global__ void __launch_bounds__(256, 2) hgemm(
    const h16* __restrict__ Af, const h16* __restrict__ Bf,
    void* __restrict__ Cv, int K, int lda, int ldb, int ldc,
    int mode, int ofp16, int bnn, long long sA, long long sB, long long sC)
{
    const int bz = blockIdx.z;
    Af += (size_t)bz * sA;
    Bf += (size_t)bz * sB;

    int row0, col0;
    if (mode == 1) {
        const int t = blockIdx.x;
        int r = (int)((__fsqrt_rn(8.f * (float)t + 1.f) - 1.f) * 0.5f);
        while ((r + 1) * (r + 2) / 2 <= t) r++;
        while (r * (r + 1) / 2 > t) r--;
        row0 = r * 128;
        col0 = (t - r * (r + 1) / 2) * 128;
    } else if (mode == 2) {
        const int by = (int)gridDim.y - 1 - (int)blockIdx.y;  // heavy first
        row0 = by * 128;
        col0 = blockIdx.x * 128;
    } else {
        row0 = blockIdx.y * 128;
        col0 = blockIdx.x * 128;
    }
    const int kend = (mode == 2) ? (row0 + 128) : K;
    const int nc = kend / KC;

    extern __shared__ char smc[];
    const uint32_t smb = smem_u32(smc);
    const int tid  = threadIdx.x;
    const int lane = tid & 31;
    const int wid  = tid >> 5;
    const int m0 = (wid & 1) * 64;
    const int n0 = (wid >> 1) * 32;

    float acc[4][4][4];
#pragma unroll
    for (int i = 0; i < 4; i++)
#pragma unroll
        for (int j = 0; j < 4; j++)
#pragma unroll
            for (int q = 0; q < 4; q++) acc[i][j][q] = 0.f;

    const int lch  = tid & 7;
    const int lr0  = tid >> 3;
    const int lch2 = tid & 15;
    const int lr2  = tid >> 4;

    auto do_load = [&](int st, int k0) {
        const uint32_t sb = smb + (uint32_t)st * STGB;
        const h16* pA = Af + (size_t)row0 * lda + k0;
#pragma unroll
        for (int j = 0; j < 4; j++) {
            const int row = lr0 + j * 32;
            CP_ASYNC16(sb + (uint32_t)(row * ROWB + lch * 16),
                       pA + (size_t)row * lda + lch * 8);
        }
        if (!bnn) {
            const h16* pB = Bf + (size_t)col0 * ldb + k0;
#pragma unroll
            for (int j = 0; j < 4; j++) {
                const int row = lr0 + j * 32;
                CP_ASYNC16(sb + MATB + (uint32_t)(row * ROWB + lch * 16),
                           pB + (size_t)row * ldb + lch * 8);
            }
        } else {
            const h16* pB = Bf + (size_t)k0 * ldb + col0;
#pragma unroll
            for (int j = 0; j < 4; j++) {
                const int row = lr2 + j * 16;
                CP_ASYNC16(sb + MATB + (uint32_t)(row * ROWBB + lch2 * 16),
                           pB + (size_t)row * ldb + lch2 * 8);
            }
        }
    };

    do_load(0, 0);
    CP_COMMIT();
    do_load(1, KC);
    CP_COMMIT();

    for (int c = 0; c < nc; c++) {
        CP_WAIT1();
        __syncthreads();
        if (c + 2 < nc) do_load((c + 2) % NSTG, (c + 2) * KC);
        CP_COMMIT();

        const uint32_t base = smb + (uint32_t)(c % NSTG) * STGB;
#pragma unroll
        for (int kk = 0; kk < 4; kk++) {
            uint32_t a[4][4];
#pragma unroll
            for (int mi = 0; mi < 4; mi++) {
                const uint32_t ad = base +
                    (uint32_t)((m0 + mi * 16 + (lane & 15)) * ROWB +
                               (kk * 2 + (lane >> 4)) * 16);
                ldsm4(a[mi][0], a[mi][1], a[mi][2], a[mi][3], ad);
            }
            uint32_t bb[4][2];
            if (!bnn) {
#pragma unroll
                for (int np = 0; np < 2; np++) {
                    const int rb = n0 + np * 16 + (lane & 7) + ((lane >> 4) << 3);
                    const int ch = kk * 2 + ((lane >> 3) & 1);
                    const uint32_t ad = base + MATB +
                        (uint32_t)(rb * ROWB + ch * 16);
                    ldsm4(bb[np*2][0], bb[np*2][1],
                          bb[np*2+1][0], bb[np*2+1][1], ad);
                }
            } else {
#pragma unroll
                for (int g = 0; g < 2; g++) {
                    const uint32_t ad = base + MATB +
                        (uint32_t)((kk * 16 + (lane & 15)) * ROWBB +
                                   (n0 + g * 16 + ((lane >> 4) << 3)) * 2);
                    ldsm4t(bb[g*2][0], bb[g*2][1],
                           bb[g*2+1][0], bb[g*2+1][1], ad);
                }
            }
#pragma unroll
            for (int mi = 0; mi < 4; mi++)
#pragma unroll
                for (int ni = 0; ni < 4; ni++)
                    mma16816(acc[mi][ni], a[mi], bb[ni]);
        }
    }

    const int er = lane >> 2;
    const int ec = (lane & 3) * 2;
    if (!ofp16) {
        float* C = (float*)Cv + (size_t)bz * sC;
#pragma unroll
        for (int mi = 0; mi < 4; mi++) {
            const int r = row0 + m0 + mi * 16 + er;
#pragma unroll
            for (int ni = 0; ni < 4; ni++) {
                const int cc = col0 + n0 + ni * 8 + ec;
                *(float2*)&C[(size_t)r * ldc + cc] =
                    make_float2(acc[mi][ni][0], acc[mi][ni][1]);
                *(float2*)&C[(size_t)(r + 8) * ldc + cc] =
                    make_float2(acc[mi][ni][2], acc[mi][ni][3]);
            }
        }
    } else {
        h16* C = (h16*)Cv + (size_t)bz * sC;
#pragma unroll
        for (int mi = 0; mi < 4; mi++) {
            const int r = row0 + m0 + mi * 16 + er;
#pragma unroll
            for (int ni = 0; ni < 4; ni++) {
                const int cc = col0 + n0 + ni * 8 + ec;
                __half2 h0 = __floats2half2_rn(acc[mi][ni][0], acc[mi][ni][1]);
                __half2 h1 = __floats2half2_rn(acc[mi][ni][2], acc[mi][ni][3]);
                *(__half2*)&C[(size_t)r * ldc + cc] = h0;
                *(__half2*)&C[(size_t)(r + 8) * ldc + cc] = h1;
            }
        }
    }
}

// ---------------- fused prep: x fp16 + Wk fp16 + Wq^T + Wv^T ----------------
#define NXB (BT * Dsz / 1024)        // 8192 blocks for x
#define NWB (Dsz * Dsz / 1024)       // 1024 blocks per weight

__global__ void __launch_bounds__(256) prep(
    const float* __restrict__ x,  const float* __restrict__ Wq,
    const float* __restrict__ Wk, const float* __restrict__ Wv,
    h16* __restrict__ xf, h16* __restrict__ wqt,
    h16* __restrict__ wkf, h16* __restrict__ wvt /* ld 2*Dsz */)
{
    __shared__ float tile[32][33];
    const int bid = blockIdx.x;
    const int tid = threadIdx.x;

    if (bid < NXB + NWB) {
        // straight fp32 -> fp16 convert (x, then Wk)
        const float* in = (bid < NXB) ? x : Wk;
        h16* o = (bid < NXB) ? xf : wkf;
        const int i = (bid < NXB ? bid : bid - NXB) * 256 + tid;
        float4 v = ((const float4*)in)[i];
        __half2 p0 = __floats2half2_rn(v.x, v.y);
        __half2 p1 = __floats2half2_rn(v.z, v.w);
        uint2 u;
        u.x = *(uint32_t*)&p0;
        u.y = *(uint32_t*)&p1;
        ((uint2*)o)[i] = u;
    } else {
        // transpose-convert: Wq -> wqt (ld Dsz) or Wv -> wvt (ld 2*Dsz)
        const int t = bid - (NXB + NWB);
        const bool isq = t < NWB;
        const int tt = isq ? t : t - NWB;
        const float* w = isq ? Wq : Wv;
        h16* o = isq ? wqt : wvt;
        const int ldo = isq ? Dsz : 2 * Dsz;
        const int d0 = (tt & 31) * 32;
        const int o0 = (tt >> 5) * 32;
        const int tx = tid & 31, ty = tid >> 5;
#pragma unroll
        for (int j = ty; j < 32; j += 8)
            tile[j][tx] = w[(size_t)(o0 + j) * Dsz + d0 + tx];
        __syncthreads();
#pragma unroll
        for (int j = ty; j < 32; j += 8)
            o[(size_t)(d0 + j) * ldo + o0 + tx] = __float2half_rn(tile[tx][j]);
    }
}

// ---------------- warp-per-row causal softmax (fp16 S -> fp16 P) ------------
__device__ __forceinline__ float warp_max_f(float v) {
#pragma unroll
    for (int o = 16; o; o >>= 1) v = fmaxf(v, __shfl_xor_sync(0xffffffffu, v, o));
    return v;
}
__device__ __forceinline__ float warp_sum_f(float v) {
#pragma unroll
    for (int o = 16; o; o >>= 1) v += __shfl_xor_sync(0xffffffffu, v, o);
    return v;
}

#define SMX_SMEM (8 * Tsz * 4)   // 8 warps x 2048 floats = 64 KB

__global__ void __launch_bounds__(256) softmax_pf(
    const h16* __restrict__ S, h16* __restrict__ pf)
{
    extern __shared__ float esb[];
    const int b = blockIdx.y;
    const int w = threadIdx.x >> 5;
    const int lane = threadIdx.x & 31;
    const int r = blockIdx.x * 8 + w;
    float* es = esb + w * Tsz;
    const h16* row = S + ((size_t)b * Tsz + r) * Tsz;
    h16* pr = pf + ((size_t)b * Tsz + r) * Tsz;
    const int blk_end = ((r >> 7) + 1) << 7;
    const int n8 = blk_end >> 3;
    const float scale = 0.03125f;  // 1/sqrt(1024)

    // pass 1: gmem -> smem (raw fp32) + masked max
    float m = -INFINITY;
    for (int i8 = lane; i8 < n8; i8 += 32) {
        uint4 u = ((const uint4*)row)[i8];
        float2 f0 = __half22float2(*(__half2*)&u.x);
        float2 f1 = __half22float2(*(__half2*)&u.y);
        float2 f2 = __half22float2(*(__half2*)&u.z);
        float2 f3 = __half22float2(*(__half2*)&u.w);
        ((float4*)es)[i8 * 2 + 0] = make_float4(f0.x, f0.y, f1.x, f1.y);
        ((float4*)es)[i8 * 2 + 1] = make_float4(f2.x, f2.y, f3.x, f3.y);
        const int base = i8 << 3;
        if (base + 7 <= r) {
            m = fmaxf(m, fmaxf(fmaxf(f0.x, f0.y), fmaxf(f1.x, f1.y)));
            m = fmaxf(m, fmaxf(fmaxf(f2.x, f2.y), fmaxf(f3.x, f3.y)));
        } else {
            float vv[8] = {f0.x, f0.y, f1.x, f1.y, f2.x, f2.y, f3.x, f3.y};
#pragma unroll
            for (int j = 0; j < 8; j++)
                if (base + j <= r) m = fmaxf(m, vv[j]);
        }
    }
    m = warp_max_f(m);

    // pass 2: smem exp in place + sum (each lane owns its i8 slots)
    float ssum = 0.f;
    for (int i8 = lane; i8 < n8; i8 += 32) {
        float4 v0 = ((const float4*)es)[i8 * 2 + 0];
        float4 v1 = ((const float4*)es)[i8 * 2 + 1];
        float vv[8] = {v0.x, v0.y, v0.z, v0.w, v1.x, v1.y, v1.z, v1.w};
        const int base = i8 << 3;
        float e[8];
#pragma unroll
        for (int j = 0; j < 8; j++) {
            e[j] = (base + j <= r) ? __expf((vv[j] - m) * scale) : 0.f;
            ssum += e[j];
        }
        ((float4*)es)[i8 * 2 + 0] = make_float4(e[0], e[1], e[2], e[3]);
        ((float4*)es)[i8 * 2 + 1] = make_float4(e[4], e[5], e[6], e[7]);
    }
    ssum = warp_sum_f(ssum);
    const float inv = 1.f / ssum;

    // pass 3: normalize + write fp16 (tail zeros come for free)
    for (int i8 = lane; i8 < n8; i8 += 32) {
        float4 e0 = ((const float4*)es)[i8 * 2 + 0];
        float4 e1 = ((const float4*)es)[i8 * 2 + 1];
        __half2 h0 = __floats2half2_rn(e0.x * inv, e0.y * inv);
        __half2 h1 = __floats2half2_rn(e0.z * inv, e0.w * inv);
        __half2 h2 = __floats2half2_rn(e1.x * inv, e1.y * inv);
        __half2 h3 = __floats2half2_rn(e1.z * inv, e1.w * inv);
        uint4 u;
        u.x = *(uint32_t*)&h0;
        u.y = *(uint32_t*)&h1;
        u.z = *(uint32_t*)&h2;
        u.w = *(uint32_t*)&h3;
        ((uint4*)pr)[i8] = u;
    }
}

// ---------------- launch ------------------------------------------------------
extern "C" void kernel_launch(void* const* d_in, const int* in_sizes, int n_in,
                              void* d_out, int out_size)
{
    (void)in_sizes; (void)n_in; (void)out_size;
    const float* x  = (const float*)d_in[0];
    const float* Wq = (const float*)d_in[1];
    const float* Wk = (const float*)d_in[2];
    const float* Wv = (const float*)d_in[3];
    float* out = (float*)d_out;

    h16 *s, *xf, *wqt, *wk, *bc, *av, *pf;
    cudaGetSymbolAddress((void**)&s,   g_s);
    cudaGetSymbolAddress((void**)&xf,  g_xf);
    cudaGetSymbolAddress((void**)&wqt, g_wqt);
    cudaGetSymbolAddress((void**)&wk,  g_wk);
    cudaGetSymbolAddress((void**)&bc,  g_bc);
    cudaGetSymbolAddress((void**)&av,  g_av);
    cudaGetSymbolAddress((void**)&pf,  g_pf);

    cudaFuncSetAttribute(hgemm, cudaFuncAttributeMaxDynamicSharedMemorySize,
                         SMEMB);
    cudaFuncSetAttribute(softmax_pf,
                         cudaFuncAttributeMaxDynamicSharedMemorySize, SMX_SMEM);

    // fused conversions: x, Wk straight; Wq^T -> wqt; Wv^T -> bc cols [1024,2048)
    prep<<<NXB + 3 * NWB, 256>>>(x, Wq, Wk, Wv, xf, wqt, wk, bc + Dsz);

    // M = Wq^T @ Wk -> B' cols [0,1024)   (NN, fp16 out, ldc=2048)
    hgemm<<<dim3(Dsz / 128, Dsz / 128, 1), 256, SMEMB>>>(
        wqt, wk, bc, Dsz, Dsz, Dsz, 2 * Dsz, 0, 1, 1, 0, 0, 0);

    // [A | V] = x @ B'   [8192, 2048] (NN, fp16 out)
    hgemm<<<dim3(2 * Dsz / 128, BT / 128, 1), 256, SMEMB>>>(
        xf, bc, av, Dsz, Dsz, 2 * Dsz, 2 * Dsz, 0, 1, 1, 0, 0, 0);

    const h16* am = av;             // A, row stride 2048
    const h16* vp = av + Dsz;       // V, row stride 2048

    // S = A @ x^T per batch (NT, triangular tile grid), fp16 out
    const int ntiles = (Tsz / 128) * (Tsz / 128 + 1) / 2;   // 136
    hgemm<<<dim3(ntiles, 1, Bsz), 256, SMEMB>>>(
        am, xf, s, Dsz, 2 * Dsz, Dsz, Tsz, 1, 1, 0,
        (long long)Tsz * 2 * Dsz, (long long)Tsz * Dsz,
        (long long)Tsz * Tsz);

    // causal softmax (warp per row) -> P fp16 (tail zero-filled)
    softmax_pf<<<dim3(Tsz / 8, Bsz), 256, SMX_SMEM>>>(s, pf);

    // O = P @ V (NN: B=V rows stride 2048, K clipped to row0+128), fp32 out
    hgemm<<<dim3(Dsz / 128, Tsz / 128, Bsz), 256, SMEMB>>>(
        pf, vp, out, Tsz, Tsz, 2 * Dsz, Dsz, 2, 0, 1,
        (long long)Tsz * Tsz, (long long)Tsz * 2 * Dsz,
        (long long)Tsz * Dsz);
}

// round 12
// speedup vs baseline: 1.3238x; 1.0561x over previous
#include <cuda_runtime.h>
#include <cuda_fp16.h>
#include <stdint.h>
#include <math.h>

#define Bsz 4
#define Tsz 2048
#define Dsz 1024
#define BT  (Bsz * Tsz)

typedef __half h16;

// ---------------- scratch (__device__ globals; allocation-free rule) -------
__device__ __align__(16) h16 g_xf[(size_t)BT * Dsz];
__device__ __align__(16) h16 g_wqt[(size_t)Dsz * Dsz];       // Wq^T fp16
__device__ __align__(16) h16 g_wk[(size_t)Dsz * Dsz];        // Wk fp16
__device__ __align__(16) h16 g_mp[4][(size_t)Dsz * Dsz];     // M split-K partials
__device__ __align__(16) h16 g_bc[(size_t)Dsz * 2 * Dsz];    // B' = [M | Wv^T]
__device__ __align__(16) h16 g_av[(size_t)BT * 2 * Dsz];     // [A | V]
__device__ __align__(16) h16 g_pf[(size_t)Bsz * Tsz * Tsz];  // P (unnormalized)
__device__ __align__(16) float g_rsum[(size_t)Bsz * Tsz];    // softmax row sums

// ---------------- low-level helpers (plain sm_80-era PTX only) --------------
__device__ __forceinline__ uint32_t smem_u32(const void* p) {
    uint32_t a;
    asm("{ .reg .u64 t; cvta.to.shared.u64 t, %1; cvt.u32.u64 %0, t; }"
        : "=r"(a) : "l"(p));
    return a;
}

#define CP_ASYNC16(dst, src) \
    asm volatile("cp.async.cg.shared.global [%0], [%1], 16;" \
                 :: "r"(dst), "l"(src))
#define CP_COMMIT() asm volatile("cp.async.commit_group;")
#define CP_WAIT1()  asm volatile("cp.async.wait_group 1;")

__device__ __forceinline__ void ldsm4(uint32_t& r0, uint32_t& r1,
                                      uint32_t& r2, uint32_t& r3,
                                      uint32_t addr) {
    asm volatile("ldmatrix.sync.aligned.m8n8.x4.shared.b16 {%0,%1,%2,%3}, [%4];"
                 : "=r"(r0), "=r"(r1), "=r"(r2), "=r"(r3) : "r"(addr));
}

__device__ __forceinline__ void ldsm4t(uint32_t& r0, uint32_t& r1,
                                       uint32_t& r2, uint32_t& r3,
                                       uint32_t addr) {
    asm volatile(
        "ldmatrix.sync.aligned.m8n8.x4.trans.shared.b16 {%0,%1,%2,%3}, [%4];"
        : "=r"(r0), "=r"(r1), "=r"(r2), "=r"(r3) : "r"(addr));
}

__device__ __forceinline__ void mma16816(float* d, const uint32_t* a,
                                         const uint32_t* b) {
    asm volatile(
        "mma.sync.aligned.m16n8k16.row.col.f32.f16.f16.f32 "
        "{%0,%1,%2,%3}, {%4,%5,%6,%7}, {%8,%9}, {%0,%1,%2,%3};"
        : "+f"(d[0]), "+f"(d[1]), "+f"(d[2]), "+f"(d[3])
        : "r"(a[0]), "r"(a[1]), "r"(a[2]), "r"(a[3]), "r"(b[0]), "r"(b[1]));
}

// ---------------- HMMA GEMM (proven at-ceiling config) -----------------------
// C[M,N] = A[M,K] * op(B).  bnn=0: B is [N,K] (NT).  bnn=1: B is [K,N] (NN).
// mode 0: full grid.  mode 1: triangular tile index.  mode 2: kend=row0+128.
// ofp16: fp16 C.  oexp: exp epilogue (fp16 P + atomic row sums, causal mask).
// oscale: fp32 C scaled by 1/rsum[row].
#define KC     64
#define ROWB   144
#define ROWBB  272
#define MATB   (128 * ROWB)
#define STGB   (2 * MATB)
#define NSTG   3
#define SMEMB  (NSTG * STGB)     // 110592 B
#define SMSCALE 0.03125f         // 1/sqrt(1024)

__global__ void __launch_bounds__(256, 2) hgemm(
    const h16* __restrict__ Af, const h16* __restrict__ Bf,
    void* __restrict__ Cv, float* __restrict__ rsum,
    int K, int lda, int ldb, int ldc,
    int mode, int ofp16, int bnn, int oexp, int oscale,
    long long sA, long long sB, long long sC)
{
    const int bz = blockIdx.z;
    Af += (size_t)bz * sA;
    Bf += (size_t)bz * sB;

    int row0, col0;
    if (mode == 1) {
        const int t = blockIdx.x;
        int r = (int)((__fsqrt_rn(8.f * (float)t + 1.f) - 1.f) * 0.5f);
        while ((r + 1) * (r + 2) / 2 <= t) r++;
        while (r * (r + 1) / 2 > t) r--;
        row0 = r * 128;
        col0 = (t - r * (r + 1) / 2) * 128;
    } else if (mode == 2) {
        const int by = (int)gridDim.y - 1 - (int)blockIdx.y;  // heavy first
        row0 = by * 128;
        col0 = blockIdx.x * 128;
    } else {
        row0 = blockIdx.y * 128;
        col0 = blockIdx.x * 128;
    }
    const int kend = (mode == 2) ? (row0 + 128) : K;
    const int nc = kend / KC;

    extern __shared__ char smc[];
    const uint32_t smb = smem_u32(smc);
    const int tid  = threadIdx.x;
    const int lane = tid & 31;
    const int wid  = tid >> 5;
    const int m0 = (wid & 1) * 64;
    const int n0 = (wid >> 1) * 32;

    float acc[4][4][4];
#pragma unroll
    for (int i = 0; i < 4; i++)
#pragma unroll
        for (int j = 0; j < 4; j++)
#pragma unroll
            for (int q = 0; q < 4; q++) acc[i][j][q] = 0.f;

    const int lch  = tid & 7;
    const int lr0  = tid >> 3;
    const int lch2 = tid & 15;
    const int lr2  = tid >> 4;

    auto do_load = [&](int st, int k0) {
        const uint32_t sb = smb + (uint32_t)st * STGB;
        const h16* pA = Af + (size_t)row0 * lda + k0;
#pragma unroll
        for (int j = 0; j < 4; j++) {
            const int row = lr0 + j * 32;
            CP_ASYNC16(sb + (uint32_t)(row * ROWB + lch * 16),
                       pA + (size_t)row * lda + lch * 8);
        }
        if (!bnn) {
            const h16* pB = Bf + (size_t)col0 * ldb + k0;
#pragma unroll
            for (int j = 0; j < 4; j++) {
                const int row = lr0 + j * 32;
                CP_ASYNC16(sb + MATB + (uint32_t)(row * ROWB + lch * 16),
                           pB + (size_t)row * ldb + lch * 8);
            }
        } else {
            const h16* pB = Bf + (size_t)k0 * ldb + col0;
#pragma unroll
            for (int j = 0; j < 4; j++) {
                const int row = lr2 + j * 16;
                CP_ASYNC16(sb + MATB + (uint32_t)(row * ROWBB + lch2 * 16),
                           pB + (size_t)row * ldb + lch2 * 8);
            }
        }
    };

    do_load(0, 0);
    CP_COMMIT();
    do_load(1, KC);
    CP_COMMIT();

    for (int c = 0; c < nc; c++) {
        CP_WAIT1();
        __syncthreads();
        if (c + 2 < nc) do_load((c + 2) % NSTG, (c + 2) * KC);
        CP_COMMIT();

        const uint32_t base = smb + (uint32_t)(c % NSTG) * STGB;
#pragma unroll
        for (int kk = 0; kk < 4; kk++) {
            uint32_t a[4][4];
#pragma unroll
            for (int mi = 0; mi < 4; mi++) {
                const uint32_t ad = base +
                    (uint32_t)((m0 + mi * 16 + (lane & 15)) * ROWB +
                               (kk * 2 + (lane >> 4)) * 16);
                ldsm4(a[mi][0], a[mi][1], a[mi][2], a[mi][3], ad);
            }
            uint32_t bb[4][2];
            if (!bnn) {
#pragma unroll
                for (int np = 0; np < 2; np++) {
                    const int rb = n0 + np * 16 + (lane & 7) + ((lane >> 4) << 3);
                    const int ch = kk * 2 + ((lane >> 3) & 1);
                    const uint32_t ad = base + MATB +
                        (uint32_t)(rb * ROWB + ch * 16);
                    ldsm4(bb[np*2][0], bb[np*2][1],
                          bb[np*2+1][0], bb[np*2+1][1], ad);
                }
            } else {
#pragma unroll
                for (int g = 0; g < 2; g++) {
                    const uint32_t ad = base + MATB +
                        (uint32_t)((kk * 16 + (lane & 15)) * ROWBB +
                                   (n0 + g * 16 + ((lane >> 4) << 3)) * 2);
                    ldsm4t(bb[g*2][0], bb[g*2][1],
                           bb[g*2+1][0], bb[g*2+1][1], ad);
                }
            }
#pragma unroll
            for (int mi = 0; mi < 4; mi++)
#pragma unroll
                for (int ni = 0; ni < 4; ni++)
                    mma16816(acc[mi][ni], a[mi], bb[ni]);
        }
    }

    // ---------------- epilogues ----------------
    const int er = lane >> 2;
    const int ec = (lane & 3) * 2;

    if (oexp) {
        // P_unnorm = exp(S*scale) with causal mask; warp-reduced row sums
        h16* C = (h16*)Cv + (size_t)bz * sC;
        float* rs = rsum + (size_t)bz * Tsz;
#pragma unroll
        for (int mi = 0; mi < 4; mi++) {
            const int rlo = row0 + m0 + mi * 16 + er;
            const int rhi = rlo + 8;
            float slo = 0.f, shi = 0.f;
#pragma unroll
            for (int ni = 0; ni < 4; ni++) {
                const int cc = col0 + n0 + ni * 8 + ec;
                float p0 = (cc     <= rlo) ? __expf(acc[mi][ni][0] * SMSCALE) : 0.f;
                float p1 = (cc + 1 <= rlo) ? __expf(acc[mi][ni][1] * SMSCALE) : 0.f;
                float p2 = (cc     <= rhi) ? __expf(acc[mi][ni][2] * SMSCALE) : 0.f;
                float p3 = (cc + 1 <= rhi) ? __expf(acc[mi][ni][3] * SMSCALE) : 0.f;
                __half2 h0 = __floats2half2_rn(p0, p1);
                __half2 h1 = __floats2half2_rn(p2, p3);
                *(__half2*)&C[(size_t)rlo * ldc + cc] = h0;
                *(__half2*)&C[(size_t)rhi * ldc + cc] = h1;
                slo += p0 + p1;
                shi += p2 + p3;
            }
            slo += __shfl_xor_sync(0xffffffffu, slo, 1);
            slo += __shfl_xor_sync(0xffffffffu, slo, 2);
            shi += __shfl_xor_sync(0xffffffffu, shi, 1);
            shi += __shfl_xor_sync(0xffffffffu, shi, 2);
            if ((lane & 3) == 0) {
                atomicAdd(&rs[rlo], slo);
                atomicAdd(&rs[rhi], shi);
            }
        }
    } else if (!ofp16) {
        float* C = (float*)Cv + (size_t)bz * sC;
        const float* rs = rsum + (size_t)bz * Tsz;
#pragma unroll
        for (int mi = 0; mi < 4; mi++) {
            const int r = row0 + m0 + mi * 16 + er;
            float ilo = 1.f, ihi = 1.f;
            if (oscale) {
                ilo = __fdividef(1.f, rs[r]);
                ihi = __fdividef(1.f, rs[r + 8]);
            }
#pragma unroll
            for (int ni = 0; ni < 4; ni++) {
                const int cc = col0 + n0 + ni * 8 + ec;
                *(float2*)&C[(size_t)r * ldc + cc] =
                    make_float2(acc[mi][ni][0] * ilo, acc[mi][ni][1] * ilo);
                *(float2*)&C[(size_t)(r + 8) * ldc + cc] =
                    make_float2(acc[mi][ni][2] * ihi, acc[mi][ni][3] * ihi);
            }
        }
    } else {
        h16* C = (h16*)Cv + (size_t)bz * sC;
#pragma unroll
        for (int mi = 0; mi < 4; mi++) {
            const int r = row0 + m0 + mi * 16 + er;
#pragma unroll
            for (int ni = 0; ni < 4; ni++) {
                const int cc = col0 + n0 + ni * 8 + ec;
                __half2 h0 = __floats2half2_rn(acc[mi][ni][0], acc[mi][ni][1]);
                __half2 h1 = __floats2half2_rn(acc[mi][ni][2], acc[mi][ni][3]);
                *(__half2*)&C[(size_t)r * ldc + cc] = h0;
                *(__half2*)&C[(size_t)(r + 8) * ldc + cc] = h1;
            }
        }
    }
}

// ---------------- fused prep: x fp16 + Wk fp16 + Wq^T + Wv^T ----------------
#define NXB (BT * Dsz / 1024)        // 8192 blocks for x
#define NWB (Dsz * Dsz / 1024)       // 1024 blocks per weight

__global__ void __launch_bounds__(256) prep(
    const float* __restrict__ x,  const float* __restrict__ Wq,
    const float* __restrict__ Wk, const float* __restrict__ Wv,
    h16* __restrict__ xf, h16* __restrict__ wqt,
    h16* __restrict__ wkf, h16* __restrict__ wvt /* ld 2*Dsz */)
{
    __shared__ float tile[32][33];
    const int bid = blockIdx.x;
    const int tid = threadIdx.x;

    if (bid < NXB + NWB) {
        const float* in = (bid < NXB) ? x : Wk;
        h16* o = (bid < NXB) ? xf : wkf;
        const int i = (bid < NXB ? bid : bid - NXB) * 256 + tid;
        float4 v = ((const float4*)in)[i];
        __half2 p0 = __floats2half2_rn(v.x, v.y);
        __half2 p1 = __floats2half2_rn(v.z, v.w);
        uint2 u;
        u.x = *(uint32_t*)&p0;
        u.y = *(uint32_t*)&p1;
        ((uint2*)o)[i] = u;
    } else {
        const int t = bid - (NXB + NWB);
        const bool isq = t < NWB;
        const int tt = isq ? t : t - NWB;
        const float* w = isq ? Wq : Wv;
        h16* o = isq ? wqt : wvt;
        const int ldo = isq ? Dsz : 2 * Dsz;
        const int d0 = (tt & 31) * 32;
        const int o0 = (tt >> 5) * 32;
        const int tx = tid & 31, ty = tid >> 5;
#pragma unroll
        for (int j = ty; j < 32; j += 8)
            tile[j][tx] = w[(size_t)(o0 + j) * Dsz + d0 + tx];
        __syncthreads();
#pragma unroll
        for (int j = ty; j < 32; j += 8)
            o[(size_t)(d0 + j) * ldo + o0 + tx] = __float2half_rn(tile[tx][j]);
    }
}

// ---------------- conv_m: sum 4 fp16 split-K partials -> B' cols [0,1024) ---
__global__ void __launch_bounds__(256) conv_m(
    const h16* __restrict__ mp, h16* __restrict__ bc)
{
    const int i = blockIdx.x * 256 + threadIdx.x;   // 0..131071 (uint4 units)
    const int row = i >> 7;
    const int cb  = i & 127;
    const uint4* p = (const uint4*)mp;
    const int ps = (Dsz * Dsz) / 8;                  // partial stride in uint4

    float2 f[4] = {{0,0},{0,0},{0,0},{0,0}};
#pragma unroll
    for (int k = 0; k < 4; k++) {
        uint4 u = p[(size_t)k * ps + i];
        const __half2* h = (const __half2*)&u;
#pragma unroll
        for (int j = 0; j < 4; j++) {
            float2 v = __half22float2(h[j]);
            f[j].x += v.x;
            f[j].y += v.y;
        }
    }
    uint4 o;
    __half2* oh = (__half2*)&o;
#pragma unroll
    for (int j = 0; j < 4; j++)
        oh[j] = __floats2half2_rn(f[j].x, f[j].y);
    ((uint4*)bc)[(size_t)row * 256 + cb] = o;
}

// ---------------- launch ------------------------------------------------------
extern "C" void kernel_launch(void* const* d_in, const int* in_sizes, int n_in,
                              void* d_out, int out_size)
{
    (void)in_sizes; (void)n_in; (void)out_size;
    const float* x  = (const float*)d_in[0];
    const float* Wq = (const float*)d_in[1];
    const float* Wk = (const float*)d_in[2];
    const float* Wv = (const float*)d_in[3];
    float* out = (float*)d_out;

    h16 *xf, *wqt, *wk, *mp, *bc, *av, *pf;
    float* rsum;
    cudaGetSymbolAddress((void**)&xf,   g_xf);
    cudaGetSymbolAddress((void**)&wqt,  g_wqt);
    cudaGetSymbolAddress((void**)&wk,   g_wk);
    cudaGetSymbolAddress((void**)&mp,   g_mp);
    cudaGetSymbolAddress((void**)&bc,   g_bc);
    cudaGetSymbolAddress((void**)&av,   g_av);
    cudaGetSymbolAddress((void**)&pf,   g_pf);
    cudaGetSymbolAddress((void**)&rsum, g_rsum);

    cudaFuncSetAttribute(hgemm, cudaFuncAttributeMaxDynamicSharedMemorySize,
                         SMEMB);

    // zero softmax row sums (graph-capturable async memset)
    cudaMemsetAsync(rsum, 0, (size_t)Bsz * Tsz * sizeof(float));

    // fused conversions: x, Wk straight; Wq^T -> wqt; Wv^T -> bc cols [1024,2048)
    prep<<<NXB + 3 * NWB, 256>>>(x, Wq, Wk, Wv, xf, wqt, wk, bc + Dsz);

    // M = Wq^T @ Wk, split-K=4 over blockIdx.z -> 4 fp16 partials
    hgemm<<<dim3(Dsz / 128, Dsz / 128, 4), 256, SMEMB>>>(
        wqt, wk, mp, rsum, 256, Dsz, Dsz, Dsz, 0, 1, 1, 0, 0,
        256, (long long)256 * Dsz, (long long)Dsz * Dsz);

    // reduce partials -> B' cols [0,1024) (ldc 2048)
    conv_m<<<(Dsz * Dsz / 8) / 256, 256>>>(mp, bc);

    // [A | V] = x @ B'   [8192, 2048] (NN, fp16 out)
    hgemm<<<dim3(2 * Dsz / 128, BT / 128, 1), 256, SMEMB>>>(
        xf, bc, av, rsum, Dsz, Dsz, 2 * Dsz, 2 * Dsz, 0, 1, 1, 0, 0, 0, 0, 0);

    const h16* am = av;             // A, row stride 2048
    const h16* vp = av + Dsz;       // V, row stride 2048

    // P_unnorm = exp(scale * A @ x^T) (NT, triangular grid, fused exp+rowsum)
    const int ntiles = (Tsz / 128) * (Tsz / 128 + 1) / 2;   // 136
    hgemm<<<dim3(ntiles, 1, Bsz), 256, SMEMB>>>(
        am, xf, pf, rsum, Dsz, 2 * Dsz, Dsz, Tsz, 1, 0, 0, 1, 0,
        (long long)Tsz * 2 * Dsz, (long long)Tsz * Dsz,
        (long long)Tsz * Tsz);

    // O = (P_unnorm @ V) * (1/rowsum)  (NN, K clipped to row0+128), fp32 out
    hgemm<<<dim3(Dsz / 128, Tsz / 128, Bsz), 256, SMEMB>>>(
        pf, vp, out, rsum, Tsz, Tsz, 2 * Dsz, Dsz, 2, 0, 1, 0, 1,
        (long long)Tsz * Tsz, (long long)Tsz * 2 * Dsz,
        (long long)Tsz * Dsz);
}